// round 14
// baseline (speedup 1.0000x reference)
#include <cuda_runtime.h>
#include <cooperative_groups.h>
#include <math.h>

namespace cg = cooperative_groups;

#define Bq   4
#define Tq   2048
#define INq  64
#define Hq   256
#define Dq   512
#define G4q  1024
#define EPSq 1e-5f

// ---------------- static scratch ----------------
__device__ float g_gx0[Bq * Tq * G4q];
__device__ float g_gx1[Bq * Tq * G4q];
__device__ float g_h1 [Bq * Tq * Hq];
__device__ float g_h2 [Bq * Tq * Hq];
__device__ float g_cv [Bq * Tq * Hq];
__device__ float g_kv [Bq * Tq * G4q];
__device__ float g_at [Bq * Dq];

// chunk-ready flags: [0]=gx0(target4) [1]=h1(target8) [2]=gx1(target4) [3]=h2(target8)
__device__ int g_flags[4][Bq][16];
__device__ int g_conv_done;   // target 16

#define FMA_F32X2(d, a, b, c) \
    asm("fma.rn.f32x2 %0, %1, %2, %3;" : "=l"(d) : "l"(a), "l"(b), "l"(c))

__device__ __forceinline__ float hsum_f32x2(unsigned long long v) {
    float lo, hi;
    asm("mov.b64 {%0, %1}, %2;" : "=f"(lo), "=f"(hi) : "l"(v));
    return lo + hi;
}
__device__ __forceinline__ float tanha(float x) {
    float y; asm("tanh.approx.f32 %0, %1;" : "=f"(y) : "f"(x)); return y;
}
__device__ __forceinline__ float sigt(float x) {
    return fmaf(0.5f, tanha(0.5f * x), 0.5f);
}

// ---------------- mbarrier / st.async helpers ----------------
#define MBAR_WAIT_ACQ_CLUSTER(addr, par) do {                                    \
    unsigned _done;                                                              \
    asm volatile("{\n\t.reg .pred P;\n\t"                                        \
        "mbarrier.try_wait.parity.acquire.cluster.shared::cta.b64 P, [%1], %2;\n\t" \
        "selp.b32 %0, 1, 0, P;\n\t}"                                             \
        : "=r"(_done) : "r"(addr), "r"(par) : "memory");                         \
    while (!_done) {                                                             \
        asm volatile("{\n\t.reg .pred P;\n\t"                                    \
            "mbarrier.try_wait.parity.acquire.cluster.shared::cta.b64 P, [%1], %2, 0x989680;\n\t" \
            "selp.b32 %0, 1, 0, P;\n\t}"                                         \
            : "=r"(_done) : "r"(addr), "r"(par) : "memory");                     \
    }                                                                            \
} while (0)

#define MBAR_ARM(addr, bytes) \
    asm volatile("mbarrier.arrive.expect_tx.shared.b64 _, [%0], %1;"             \
                 :: "r"(addr), "r"(bytes) : "memory")

#define ST_ASYNC_V4(daddr, r0, r1, r2, r3, mbaraddr) \
    asm volatile("st.async.weak.shared::cluster.mbarrier::complete_tx::bytes.v4.b32 " \
                 "[%0], {%1, %2, %3, %4}, [%5];"                                 \
                 :: "r"(daddr), "r"(r0), "r"(r1), "r"(r2), "r"(r3),              \
                    "r"(mbaraddr) : "memory")

__device__ __forceinline__ uint32_t smem_u32(const void* p) {
    uint32_t a;
    asm("{ .reg .u64 t; cvta.to.shared.u64 t, %1; cvt.u32.u64 %0, t; }"
        : "=r"(a) : "l"(p));
    return a;
}
__device__ __forceinline__ uint32_t mapa_u32(uint32_t a, int r) {
    uint32_t o;
    asm("mapa.shared::cluster.u32 %0, %1, %2;" : "=r"(o) : "r"(a), "r"(r));
    return o;
}

__device__ __forceinline__ void wait_flag(volatile int* f, int target) {
    if (*f < target) { while (*f < target) {} }
    __threadfence();
}

// ---------------- scan role (R8-proven structure + chunk gating) ----------------
__device__ __forceinline__ void scan_role(
    const float* __restrict__ gx, const float* __restrict__ w_hh,
    float* __restrict__ h_out, int batch,
    volatile int* in_ready, int in_target, int* out_ready, float* dsm)
{
    float* h2s = dsm;                                     // [2][256]
    unsigned long long* mbars = (unsigned long long*)(dsm + 512);

    cg::cluster_group cluster = cg::this_cluster();
    const int rank = (int)cluster.block_rank();
    const int tid = threadIdx.x;
    const int w = tid >> 5, l = tid & 31;
    const int v  = l & 3;
    const int g  = (l >> 2) & 3;
    const int kh = l >> 4;
    const int gunit = rank * 32 + w * 4 + v;
    const int row = g * Hq + gunit;

    unsigned long long wreg[64];
    {
        const ulonglong2* wp = (const ulonglong2*)(w_hh + (size_t)row * Hq + (kh << 7));
#pragma unroll
        for (int i = 0; i < 32; i++) {
            ulonglong2 t2 = wp[i];
            wreg[2 * i]     = t2.x;
            wreg[2 * i + 1] = t2.y;
        }
    }

    if (tid < 256) { h2s[tid] = 0.f; h2s[256 + tid] = 0.f; }

    const uint32_t mb0 = smem_u32(&mbars[0]);
    const uint32_t mb1 = smem_u32(&mbars[1]);
    if (tid == 0) {
        asm volatile("mbarrier.init.shared.b64 [%0], 1;" :: "r"(mb0) : "memory");
        asm volatile("mbarrier.init.shared.b64 [%0], 1;" :: "r"(mb1) : "memory");
        MBAR_ARM(mb1, 1024);
        MBAR_ARM(mb0, 1024);
    }

    const uint32_t h0_local = smem_u32(&h2s[0]);
    const int dest = l & 7;
    uint32_t peer_h[2], peer_mb[2];
    {
        uint32_t base = mapa_u32(h0_local, dest);
        uint32_t blk = (uint32_t)((rank * 32 + w * 4) * 4);
        peer_h[0] = base + blk;
        peer_h[1] = base + 1024u + blk;
        peer_mb[0] = mapa_u32(mb0, dest);
        peer_mb[1] = mapa_u32(mb1, dest);
    }

    cluster.sync();

    const float* gx_row = gx + (size_t)batch * Tq * G4q + row;
    const bool write_out = ((l >> 2) == rank);
    const bool sender = (l < 8);
    float c0 = 0.f;

    wait_flag(in_ready, in_target);
    float cur = gx_row[0];

    for (int t = 0; t < Tq; t++) {
        if (t + 1 < Tq && ((t + 1) & 127) == 0)
            wait_flag(in_ready + ((t + 1) >> 7), in_target);
        float nxt = 0.f;
        if (t + 1 < Tq) nxt = gx_row[(size_t)(t + 1) * G4q];

        if (t > 0) {
            const uint32_t mb = (t & 1) ? mb1 : mb0;
            unsigned par = (unsigned)(((t >> 1) + ((t & 1) ^ 1)) & 1);
            MBAR_WAIT_ACQ_CLUSTER(mb, par);
            if (tid == 0 && t + 2 < Tq) MBAR_ARM(mb, 1024);
        }
        const int p = t & 1;
        const ulonglong2* hb2 = (const ulonglong2*)(h2s + (p << 8) + (kh << 7));

        unsigned long long acc0 = 0ull, acc1 = 0ull, acc2 = 0ull, acc3 = 0ull;
#pragma unroll
        for (int i = 0; i < 32; i += 2) {
            ulonglong2 hv0 = hb2[i];
            ulonglong2 hv1 = hb2[i + 1];
            FMA_F32X2(acc0, wreg[2 * i + 0], hv0.x, acc0);
            FMA_F32X2(acc1, wreg[2 * i + 1], hv0.y, acc1);
            FMA_F32X2(acc2, wreg[2 * i + 2], hv1.x, acc2);
            FMA_F32X2(acc3, wreg[2 * i + 3], hv1.y, acc3);
        }
        float partial = (hsum_f32x2(acc0) + hsum_f32x2(acc1))
                      + (hsum_f32x2(acc2) + hsum_f32x2(acc3));
        float sum = partial + __shfl_xor_sync(0xFFFFFFFFu, partial, 16);
        sum += cur;

        float si = __shfl_sync(0xFFFFFFFFu, sum, v);
        float sf = __shfl_sync(0xFFFFFFFFu, sum, v + 4);
        float sg = __shfl_sync(0xFFFFFFFFu, sum, v + 8);
        float so = __shfl_sync(0xFFFFFFFFu, sum, v + 12);

        c0 = sigt(sf) * c0 + sigt(si) * tanha(sg);
        float hnew = sigt(so) * tanha(c0);

        if (write_out)
            h_out[((size_t)batch * Tq + t) * Hq + gunit] = hnew;

        if (t + 1 < Tq) {
            unsigned hu = __float_as_uint(hnew);
            unsigned f0 = __shfl_sync(0xFFFFFFFFu, hu, 0);
            unsigned f1 = __shfl_sync(0xFFFFFFFFu, hu, 1);
            unsigned f2 = __shfl_sync(0xFFFFFFFFu, hu, 2);
            unsigned f3 = __shfl_sync(0xFFFFFFFFu, hu, 3);
            if (sender) {
                const int q = (t + 1) & 1;
                ST_ASYNC_V4(peer_h[q], f0, f1, f2, f3, peer_mb[q]);
            }
        }

        if (out_ready && (t & 127) == 127) {
            __threadfence();
            __syncthreads();
            if (tid == 0) atomicAdd(out_ready + (t >> 7), 1);
        }
        cur = nxt;
    }
    cluster.sync();
}

// ---------------- 128x64 GEMM tile (A contiguous, SMEM from dsm) ------------
__device__ __forceinline__ void tile_128x64(
    const float* __restrict__ A, int lda, const float* __restrict__ W, int K,
    const float* __restrict__ b1, const float* __restrict__ b2,
    float* __restrict__ out, int n0, float* sA, float* sB)
{
    const int tid = threadIdx.x;
    const int tx = tid & 15, ty = tid >> 4;
    const int lmA = tid & 127, khA = (tid >> 7) * 8;
    const int lnB = tid & 63,  kB  = (tid >> 6) * 4;

    float acc[8][4];
#pragma unroll
    for (int i = 0; i < 8; i++)
#pragma unroll
        for (int j = 0; j < 4; j++) acc[i][j] = 0.f;

    for (int k0 = 0; k0 < K; k0 += 16) {
#pragma unroll
        for (int half = 0; half < 2; half++) {
            int off = khA + half * 4;
            float4 vv = *(const float4*)(A + (size_t)lmA * lda + k0 + off);
            sA[(off + 0) * 128 + lmA] = vv.x; sA[(off + 1) * 128 + lmA] = vv.y;
            sA[(off + 2) * 128 + lmA] = vv.z; sA[(off + 3) * 128 + lmA] = vv.w;
        }
        float4 wv = *(const float4*)(W + (size_t)(n0 + lnB) * K + k0 + kB);
        sB[(kB + 0) * 64 + lnB] = wv.x; sB[(kB + 1) * 64 + lnB] = wv.y;
        sB[(kB + 2) * 64 + lnB] = wv.z; sB[(kB + 3) * 64 + lnB] = wv.w;
        __syncthreads();
#pragma unroll
        for (int kk = 0; kk < 16; kk++) {
            float4 a0 = *(const float4*)&sA[kk * 128 + ty * 8];
            float4 a1 = *(const float4*)&sA[kk * 128 + ty * 8 + 4];
            float4 b  = *(const float4*)&sB[kk * 64 + tx * 4];
            float av[8] = {a0.x, a0.y, a0.z, a0.w, a1.x, a1.y, a1.z, a1.w};
#pragma unroll
            for (int i = 0; i < 8; i++) {
                acc[i][0] = fmaf(av[i], b.x, acc[i][0]);
                acc[i][1] = fmaf(av[i], b.y, acc[i][1]);
                acc[i][2] = fmaf(av[i], b.z, acc[i][2]);
                acc[i][3] = fmaf(av[i], b.w, acc[i][3]);
            }
        }
        __syncthreads();
    }

    float bias[4];
#pragma unroll
    for (int j = 0; j < 4; j++) {
        int n = n0 + tx * 4 + j;
        bias[j] = b1[n] + (b2 ? b2[n] : 0.f);
    }
#pragma unroll
    for (int i = 0; i < 8; i++) {
        float4 r = make_float4(acc[i][0] + bias[0], acc[i][1] + bias[1],
                               acc[i][2] + bias[2], acc[i][3] + bias[3]);
        *(float4*)(out + (size_t)(ty * 8 + i) * G4q + n0 + tx * 4) = r;
    }
}

// ---------------- 128x64 GEMM tile, split-K A (A1[0:Ks) | A2[Ks:K)) ---------
__device__ __forceinline__ void tile_128x64_split(
    const float* __restrict__ A1, const float* __restrict__ A2,
    int lda, int Ksplit, int K,
    const float* __restrict__ W, const float* __restrict__ b1,
    float* __restrict__ out, int n0, float* sA, float* sB)
{
    const int tid = threadIdx.x;
    const int tx = tid & 15, ty = tid >> 4;
    const int lmA = tid & 127, khA = (tid >> 7) * 8;
    const int lnB = tid & 63,  kB  = (tid >> 6) * 4;

    float acc[8][4];
#pragma unroll
    for (int i = 0; i < 8; i++)
#pragma unroll
        for (int j = 0; j < 4; j++) acc[i][j] = 0.f;

    for (int k0 = 0; k0 < K; k0 += 16) {
#pragma unroll
        for (int half = 0; half < 2; half++) {
            int off = khA + half * 4;
            int kg = k0 + off;
            float4 vv;
            if (kg < Ksplit) vv = *(const float4*)(A1 + (size_t)lmA * lda + kg);
            else             vv = *(const float4*)(A2 + (size_t)lmA * lda + (kg - Ksplit));
            sA[(off + 0) * 128 + lmA] = vv.x; sA[(off + 1) * 128 + lmA] = vv.y;
            sA[(off + 2) * 128 + lmA] = vv.z; sA[(off + 3) * 128 + lmA] = vv.w;
        }
        float4 wv = *(const float4*)(W + (size_t)(n0 + lnB) * K + k0 + kB);
        sB[(kB + 0) * 64 + lnB] = wv.x; sB[(kB + 1) * 64 + lnB] = wv.y;
        sB[(kB + 2) * 64 + lnB] = wv.z; sB[(kB + 3) * 64 + lnB] = wv.w;
        __syncthreads();
#pragma unroll
        for (int kk = 0; kk < 16; kk++) {
            float4 a0 = *(const float4*)&sA[kk * 128 + ty * 8];
            float4 a1 = *(const float4*)&sA[kk * 128 + ty * 8 + 4];
            float4 b  = *(const float4*)&sB[kk * 64 + tx * 4];
            float av[8] = {a0.x, a0.y, a0.z, a0.w, a1.x, a1.y, a1.z, a1.w};
#pragma unroll
            for (int i = 0; i < 8; i++) {
                acc[i][0] = fmaf(av[i], b.x, acc[i][0]);
                acc[i][1] = fmaf(av[i], b.y, acc[i][1]);
                acc[i][2] = fmaf(av[i], b.z, acc[i][2]);
                acc[i][3] = fmaf(av[i], b.w, acc[i][3]);
            }
        }
        __syncthreads();
    }

    float bias[4];
#pragma unroll
    for (int j = 0; j < 4; j++) bias[j] = b1[n0 + tx * 4 + j];
#pragma unroll
    for (int i = 0; i < 8; i++) {
        float4 r = make_float4(acc[i][0] + bias[0], acc[i][1] + bias[1],
                               acc[i][2] + bias[2], acc[i][3] + bias[3]);
        *(float4*)(out + (size_t)(ty * 8 + i) * G4q + n0 + tx * 4) = r;
    }
}

// ---------------- chunked gx gemm role ----------------
__device__ __forceinline__ void gemm_chunk_role(
    const float* __restrict__ A0, int lda, const float* __restrict__ W,
    const float* __restrict__ b1, const float* __restrict__ b2,
    float* __restrict__ out0, int K, int slice_n0,
    volatile int* in_ready, int in_target, int* out_ready, float* dsm)
{
    float* sA = dsm;
    float* sB = dsm + 2048;
    for (int c = 0; c < 16; c++) {
        if (in_ready) wait_flag(in_ready + c, in_target);
        const float* A = A0 + (size_t)c * 128 * lda;
        float* out = out0 + (size_t)c * 128 * G4q;
        for (int j = 0; j < 4; j++)
            tile_128x64(A, lda, W, K, b1, b2, out, slice_n0 + j * 64, sA, sB);
        __threadfence();
        __syncthreads();
        if (threadIdx.x == 0) atomicAdd(out_ready + c, 1);
    }
}

// ---------------- chunked kv gemm role (trails scan1) ----------------
__device__ __forceinline__ void kv_role(
    const float* __restrict__ h2, const float* __restrict__ cv,
    const float* __restrict__ qkv_w, const float* __restrict__ qkv_b,
    float* __restrict__ kvout, int b, int slice_n0, float* dsm)
{
    float* sA = dsm;
    float* sB = dsm + 2048;
    volatile int* h2f = (volatile int*)&g_flags[3][b][0];
    wait_flag((volatile int*)&g_conv_done, 16);
    for (int c = 0; c < 16; c++) {
        wait_flag(h2f + c, 8);
        const float* A1 = h2 + (size_t)(b * Tq + c * 128) * Hq;
        const float* A2 = cv + (size_t)(b * Tq + c * 128) * Hq;
        float* out = kvout + (size_t)(b * Tq + c * 128) * G4q;
        for (int j = 0; j < 4; j++)
            tile_128x64_split(A1, A2, Hq, 256, 512,
                              qkv_w + 512 * 512, qkv_b + 512,
                              out, slice_n0 + j * 64, sA, sB);
    }
}

// ---------------- conv role (one (batch, oc-block) pair per CTA) -------------
__device__ __forceinline__ void conv_role(
    const float* __restrict__ x, const float* __restrict__ cw,
    const float* __restrict__ cb, const float* __restrict__ bg,
    const float* __restrict__ bnb, const float* __restrict__ bmean,
    const float* __restrict__ bvar, int pair, float* dsm)
{
    float* xs = dsm;              // [36][64]
    float* ws = dsm + 36 * 64;    // [64][321]
    const int tid = threadIdx.x;
    const int b = pair >> 2, ocb = (pair & 3) * 64;

    for (int idx = tid; idx < 64 * 320; idx += 256) {
        int o = idx / 320, ik = idx % 320;
        ws[o * 321 + ik] = cw[(size_t)(ocb + o) * 320 + ik];
    }

    const int o = tid & 63, gq = tid >> 6;
    const int tb = gq * 8;
    const int oc = ocb + o;
    float scl = rsqrtf(bvar[oc] + EPSq) * bg[oc];
    float sh = bnb[oc] - bmean[oc] * scl;
    float cbv = cb[oc];

    for (int tb0 = 0; tb0 < 64; tb0++) {
        const int t0 = tb0 * 32;
        __syncthreads();     // previous compute done before xs overwrite
        for (int idx = tid; idx < 36 * 64; idx += 256) {
            int tr = idx >> 6, i = idx & 63;
            int tg = t0 + tr - 2;
            xs[idx] = (tg >= 0 && tg < Tq) ? x[((size_t)b * Tq + tg) * INq + i] : 0.f;
        }
        __syncthreads();

        float acc[8];
#pragma unroll
        for (int t = 0; t < 8; t++) acc[t] = 0.f;
        for (int i = 0; i < 64; i++) {
            float xv[12];
#pragma unroll
            for (int j = 0; j < 12; j++) xv[j] = xs[(tb + j) * 64 + i];
#pragma unroll
            for (int k = 0; k < 5; k++) {
                float wv = ws[o * 321 + i * 5 + k];
#pragma unroll
                for (int t = 0; t < 8; t++) acc[t] = fmaf(xv[t + k], wv, acc[t]);
            }
        }
#pragma unroll
        for (int t = 0; t < 8; t++) {
            float y = (acc[t] + cbv) * scl + sh;
            g_cv[((size_t)b * Tq + t0 + tb + t) * Hq + oc] = y / (1.f + __expf(-y));
        }
    }
    __threadfence();
    __syncthreads();
    if (tid == 0) atomicAdd(&g_conv_done, 1);
}

// ---------------- mega kernel: everything overlapped ----------------
// grid = 128 CTAs (16 clusters x 8), 1 CTA/SM -> all co-resident.
// 0-31: layer-0 scan; 32-63: layer-1 scan (publishes h2 chunks);
// 64-79: gx1 gemm; 80-95: gx0 gemm; 96-111: conv; 112-127: kv gemm.
__global__ void __cluster_dims__(8, 1, 1) __launch_bounds__(256, 1) mega(
    const float* __restrict__ x,
    const float* __restrict__ wih0, const float* __restrict__ whh0,
    const float* __restrict__ bih0, const float* __restrict__ bhh0,
    const float* __restrict__ wih1, const float* __restrict__ whh1,
    const float* __restrict__ bih1, const float* __restrict__ bhh1,
    const float* __restrict__ cw, const float* __restrict__ cb,
    const float* __restrict__ bng, const float* __restrict__ bnb,
    const float* __restrict__ bnm, const float* __restrict__ bnv,
    const float* __restrict__ qkvw, const float* __restrict__ qkvb,
    float* __restrict__ gx0, float* __restrict__ gx1,
    float* __restrict__ h1, float* __restrict__ h2, float* __restrict__ kv)
{
    extern __shared__ float dsm[];
    const int cid = blockIdx.x >> 3;

    if (cid < 4) {
        scan_role(gx0, whh0, h1, cid,
                  (volatile int*)&g_flags[0][cid][0], 4,
                  &g_flags[1][cid][0], dsm);
    } else if (cid < 8) {
        scan_role(gx1, whh1, h2, cid - 4,
                  (volatile int*)&g_flags[2][cid - 4][0], 4,
                  &g_flags[3][cid - 4][0], dsm);
    } else if (blockIdx.x < 80) {
        const int idx = blockIdx.x - 64;
        const int b = idx & 3, slice = idx >> 2;
        gemm_chunk_role(h1 + (size_t)b * Tq * Hq, Hq, wih1, bih1, bhh1,
                        gx1 + (size_t)b * Tq * G4q, Hq, slice * 256,
                        (volatile int*)&g_flags[1][b][0], 8,
                        &g_flags[2][b][0], dsm);
    } else if (blockIdx.x < 96) {
        const int idx = blockIdx.x - 80;
        const int b = idx & 3, slice = idx >> 2;
        gemm_chunk_role(x + (size_t)b * Tq * INq, INq, wih0, bih0, bhh0,
                        gx0 + (size_t)b * Tq * G4q, INq, slice * 256,
                        nullptr, 0,
                        &g_flags[0][b][0], dsm);
    } else if (blockIdx.x < 112) {
        conv_role(x, cw, cb, bng, bnb, bnm, bnv, blockIdx.x - 96, dsm);
    } else {
        const int idx = blockIdx.x - 112;
        const int b = idx & 3, slice = idx >> 2;
        kv_role(h2, g_cv, qkvw, qkvb, kv, b, slice * 256, dsm);
    }
}

// ---------------- flag reset (graph-replay determinism) ----------------
__global__ void reset_flags() {
    if (threadIdx.x < 256) ((int*)g_flags)[threadIdx.x] = 0;
    else if (threadIdx.x == 256) g_conv_done = 0;
}

// ---------------- attention (last query row only) ----------------
__global__ __launch_bounds__(256) void attn_last(
    const float* __restrict__ qkv_w, const float* __restrict__ qkv_b)
{
    __shared__ float q[64];
    __shared__ float sc[Tq];
    __shared__ float red[256];
    __shared__ float vp[256];
    const int bh = blockIdx.x;
    const int b = bh >> 3, h = bh & 7;
    const int tid = threadIdx.x;

    if (tid < 64) {
        int row = h * 64 + tid;
        const float* wr = qkv_w + (size_t)row * Dq;
        const float* ml = g_h2 + ((size_t)b * Tq + (Tq - 1)) * Hq;
        const float* mc = g_cv + ((size_t)b * Tq + (Tq - 1)) * Hq;
        float acc = qkv_b[row];
        for (int k = 0; k < 256; k++) acc = fmaf(ml[k], wr[k], acc);
        for (int k = 0; k < 256; k++) acc = fmaf(mc[k], wr[256 + k], acc);
        q[tid] = acc * 0.125f;
    }
    __syncthreads();

    float lmax = -1e30f;
    for (int t = tid; t < Tq; t += 256) {
        const float4* kp = (const float4*)(g_kv + ((size_t)b * Tq + t) * G4q + h * 64);
        float s = 0.f;
#pragma unroll
        for (int d4 = 0; d4 < 16; d4++) {
            float4 kk = kp[d4];
            float4 qq = ((const float4*)q)[d4];
            s += kk.x * qq.x + kk.y * qq.y + kk.z * qq.z + kk.w * qq.w;
        }
        sc[t] = s;
        lmax = fmaxf(lmax, s);
    }
    red[tid] = lmax; __syncthreads();
    for (int s2 = 128; s2 > 0; s2 >>= 1) {
        if (tid < s2) red[tid] = fmaxf(red[tid], red[tid + s2]);
        __syncthreads();
    }
    float m = red[0];
    __syncthreads();

    float lsum = 0.f;
    for (int t = tid; t < Tq; t += 256) {
        float pe = __expf(sc[t] - m);
        sc[t] = pe;
        lsum += pe;
    }
    red[tid] = lsum; __syncthreads();
    for (int s2 = 128; s2 > 0; s2 >>= 1) {
        if (tid < s2) red[tid] += red[tid + s2];
        __syncthreads();
    }
    float denom = red[0];
    __syncthreads();

    const int d = tid & 63, gg = tid >> 6;
    float acc = 0.f;
    for (int t = gg * 512; t < (gg + 1) * 512; t++)
        acc = fmaf(sc[t], g_kv[((size_t)b * Tq + t) * G4q + 512 + h * 64 + d], acc);
    vp[tid] = acc; __syncthreads();
    if (tid < 64) {
        float o = (vp[tid] + vp[64 + tid] + vp[128 + tid] + vp[192 + tid]) / denom;
        g_at[b * Dq + h * 64 + tid] = o;
    }
}

// ---------------- head ----------------
__global__ __launch_bounds__(512) void head_kernel(
    const float* __restrict__ pw, const float* __restrict__ pb,
    const float* __restrict__ lng, const float* __restrict__ lnb,
    const float* __restrict__ f1w, const float* __restrict__ f1b,
    const float* __restrict__ f2w, const float* __restrict__ f2b,
    float* __restrict__ out)
{
    __shared__ float a[Dq], zn[Dq], z2[Hq], red[512];
    const int b = blockIdx.x, tid = threadIdx.x;
    a[tid] = g_at[b * Dq + tid];
    __syncthreads();

    float acc = pb[tid];
    const float* wr = pw + (size_t)tid * Dq;
    for (int k = 0; k < Dq; k++) acc = fmaf(a[k], wr[k], acc);
    float mrg = (tid < 256) ? g_h2[((size_t)b * Tq + Tq - 1) * Hq + tid]
                            : g_cv[((size_t)b * Tq + Tq - 1) * Hq + tid - 256];
    float z = acc + mrg;

    red[tid] = z; __syncthreads();
    for (int s = 256; s > 0; s >>= 1) {
        if (tid < s) red[tid] += red[tid + s];
        __syncthreads();
    }
    float mu = red[0] / 512.f;
    __syncthreads();
    float dv = z - mu;
    red[tid] = dv * dv; __syncthreads();
    for (int s = 256; s > 0; s >>= 1) {
        if (tid < s) red[tid] += red[tid + s];
        __syncthreads();
    }
    float var = red[0] / 512.f;
    __syncthreads();

    zn[tid] = dv * rsqrtf(var + EPSq) * lng[tid] + lnb[tid];
    __syncthreads();

    if (tid < 256) {
        float a2 = f1b[tid];
        const float* w1 = f1w + (size_t)tid * Dq;
        for (int k = 0; k < Dq; k++) a2 = fmaf(zn[k], w1[k], a2);
        z2[tid] = a2 / (1.f + expf(-a2));
    }
    __syncthreads();

    if (tid < 3) {
        float lg = f2b[tid];
        const float* w2 = f2w + tid * 256;
        for (int j = 0; j < 256; j++) lg = fmaf(z2[j], w2[j], lg);
        if (tid == 0)      out[b]     = tanhf(lg);
        else if (tid == 1) out[4 + b] = (lg > 20.f) ? lg : log1pf(expf(lg));
        else               out[8 + b] = 1.f / (1.f + expf(-lg));
    }
}

// ---------------- launch ----------------
extern "C" void kernel_launch(void* const* d_in, const int* in_sizes, int n_in,
                              void* d_out, int out_size) {
    const float* x     = (const float*)d_in[0];
    const float* wih0  = (const float*)d_in[1];
    const float* whh0  = (const float*)d_in[2];
    const float* bih0  = (const float*)d_in[3];
    const float* bhh0  = (const float*)d_in[4];
    const float* wih1  = (const float*)d_in[5];
    const float* whh1  = (const float*)d_in[6];
    const float* bih1  = (const float*)d_in[7];
    const float* bhh1  = (const float*)d_in[8];
    const float* cw    = (const float*)d_in[9];
    const float* cb    = (const float*)d_in[10];
    const float* bng   = (const float*)d_in[11];
    const float* bnb   = (const float*)d_in[12];
    const float* bnm   = (const float*)d_in[13];
    const float* bnv   = (const float*)d_in[14];
    const float* qkvw  = (const float*)d_in[15];
    const float* qkvb  = (const float*)d_in[16];
    const float* pw    = (const float*)d_in[17];
    const float* pbv   = (const float*)d_in[18];
    const float* lng   = (const float*)d_in[19];
    const float* lnb   = (const float*)d_in[20];
    const float* f1w   = (const float*)d_in[21];
    const float* f1b   = (const float*)d_in[22];
    const float* f2w   = (const float*)d_in[23];
    const float* f2b   = (const float*)d_in[24];
    float* out = (float*)d_out;

    float *gx0, *gx1, *h1, *h2, *kv;
    cudaGetSymbolAddress((void**)&gx0, g_gx0);
    cudaGetSymbolAddress((void**)&gx1, g_gx1);
    cudaGetSymbolAddress((void**)&h1,  g_h1);
    cudaGetSymbolAddress((void**)&h2,  g_h2);
    cudaGetSymbolAddress((void**)&kv,  g_kv);

    // mega smem: conv role needs xs(36*64) + ws(64*321) floats = ~91 KB
    const int mega_smem = (36 * 64 + 64 * 321) * 4;
    cudaFuncSetAttribute(mega, cudaFuncAttributeMaxDynamicSharedMemorySize, mega_smem);

    // 0: reset chunk flags (graph-replay determinism)
    reset_flags<<<1, 288>>>();
    // 1: fused pipeline: gx0 -> scan0 -> gx1 -> scan1 -> kv, plus conv, all
    //    chunk-overlapped inside one persistent 128-CTA kernel
    mega<<<128, 256, mega_smem>>>(x, wih0, whh0, bih0, bhh0,
                                  wih1, whh1, bih1, bhh1,
                                  cw, cb, bng, bnb, bnm, bnv,
                                  qkvw, qkvb,
                                  gx0, gx1, h1, h2, kv);
    // 2: attention (last row only)
    attn_last<<<32, 256>>>(qkvw, qkvb);
    // 3: head
    head_kernel<<<4, 512>>>(pw, pbv, lng, lnb, f1w, f1b, f2w, f2b, out);
}

// round 15
// speedup vs baseline: 1.6251x; 1.6251x over previous
#include <cuda_runtime.h>
#include <cooperative_groups.h>
#include <math.h>

namespace cg = cooperative_groups;

#define Bq   4
#define Tq   2048
#define INq  64
#define Hq   256
#define Dq   512
#define G4q  1024
#define EPSq 1e-5f

// ---------------- static scratch ----------------
__device__ float g_gx0[Bq * Tq * G4q];
__device__ float g_gx1[Bq * Tq * G4q];
__device__ float g_h1 [Bq * Tq * Hq];
__device__ float g_h2 [Bq * Tq * Hq];
__device__ float g_cv [Bq * Tq * Hq];
__device__ float g_kv [Bq * Tq * G4q];
__device__ float g_at [Bq * Dq];

// chunk-ready flags: [0]=gx0(target4) [1]=h1(target8) [2]=gx1(target4) [3]=h2(target8)
__device__ int g_flags[4][Bq][16];

#define FMA_F32X2(d, a, b, c) \
    asm("fma.rn.f32x2 %0, %1, %2, %3;" : "=l"(d) : "l"(a), "l"(b), "l"(c))

__device__ __forceinline__ float hsum_f32x2(unsigned long long v) {
    float lo, hi;
    asm("mov.b64 {%0, %1}, %2;" : "=f"(lo), "=f"(hi) : "l"(v));
    return lo + hi;
}
__device__ __forceinline__ float tanha(float x) {
    float y; asm("tanh.approx.f32 %0, %1;" : "=f"(y) : "f"(x)); return y;
}
__device__ __forceinline__ float sigt(float x) {
    return fmaf(0.5f, tanha(0.5f * x), 0.5f);
}

// ---------------- mbarrier / st.async helpers ----------------
#define MBAR_WAIT_ACQ_CLUSTER(addr, par) do {                                    \
    unsigned _done;                                                              \
    asm volatile("{\n\t.reg .pred P;\n\t"                                        \
        "mbarrier.try_wait.parity.acquire.cluster.shared::cta.b64 P, [%1], %2;\n\t" \
        "selp.b32 %0, 1, 0, P;\n\t}"                                             \
        : "=r"(_done) : "r"(addr), "r"(par) : "memory");                         \
    while (!_done) {                                                             \
        asm volatile("{\n\t.reg .pred P;\n\t"                                    \
            "mbarrier.try_wait.parity.acquire.cluster.shared::cta.b64 P, [%1], %2, 0x989680;\n\t" \
            "selp.b32 %0, 1, 0, P;\n\t}"                                         \
            : "=r"(_done) : "r"(addr), "r"(par) : "memory");                     \
    }                                                                            \
} while (0)

#define MBAR_ARM(addr, bytes) \
    asm volatile("mbarrier.arrive.expect_tx.shared.b64 _, [%0], %1;"             \
                 :: "r"(addr), "r"(bytes) : "memory")

#define ST_ASYNC_V4(daddr, r0, r1, r2, r3, mbaraddr) \
    asm volatile("st.async.weak.shared::cluster.mbarrier::complete_tx::bytes.v4.b32 " \
                 "[%0], {%1, %2, %3, %4}, [%5];"                                 \
                 :: "r"(daddr), "r"(r0), "r"(r1), "r"(r2), "r"(r3),              \
                    "r"(mbaraddr) : "memory")

__device__ __forceinline__ uint32_t smem_u32(const void* p) {
    uint32_t a;
    asm("{ .reg .u64 t; cvta.to.shared.u64 t, %1; cvt.u32.u64 %0, t; }"
        : "=r"(a) : "l"(p));
    return a;
}
__device__ __forceinline__ uint32_t mapa_u32(uint32_t a, int r) {
    uint32_t o;
    asm("mapa.shared::cluster.u32 %0, %1, %2;" : "=r"(o) : "r"(a), "r"(r));
    return o;
}

__device__ __forceinline__ void wait_flag(volatile int* f, int target) {
    if (*f < target) { while (*f < target) {} }
    __threadfence();
}

// ---------------- scan role (R8-proven structure + chunk gating) ----------------
__device__ __forceinline__ void scan_role(
    const float* __restrict__ gx, const float* __restrict__ w_hh,
    float* __restrict__ h_out, int batch,
    volatile int* in_ready, int in_target, int* out_ready, float* dsm)
{
    float* h2s = dsm;                                     // [2][256]
    unsigned long long* mbars = (unsigned long long*)(dsm + 512);

    cg::cluster_group cluster = cg::this_cluster();
    const int rank = (int)cluster.block_rank();
    const int tid = threadIdx.x;
    const int w = tid >> 5, l = tid & 31;
    const int v  = l & 3;
    const int g  = (l >> 2) & 3;
    const int kh = l >> 4;
    const int gunit = rank * 32 + w * 4 + v;
    const int row = g * Hq + gunit;

    unsigned long long wreg[64];
    {
        const ulonglong2* wp = (const ulonglong2*)(w_hh + (size_t)row * Hq + (kh << 7));
#pragma unroll
        for (int i = 0; i < 32; i++) {
            ulonglong2 t2 = wp[i];
            wreg[2 * i]     = t2.x;
            wreg[2 * i + 1] = t2.y;
        }
    }

    if (tid < 256) { h2s[tid] = 0.f; h2s[256 + tid] = 0.f; }

    const uint32_t mb0 = smem_u32(&mbars[0]);
    const uint32_t mb1 = smem_u32(&mbars[1]);
    if (tid == 0) {
        asm volatile("mbarrier.init.shared.b64 [%0], 1;" :: "r"(mb0) : "memory");
        asm volatile("mbarrier.init.shared.b64 [%0], 1;" :: "r"(mb1) : "memory");
        MBAR_ARM(mb1, 1024);
        MBAR_ARM(mb0, 1024);
    }

    const uint32_t h0_local = smem_u32(&h2s[0]);
    const int dest = l & 7;
    uint32_t peer_h[2], peer_mb[2];
    {
        uint32_t base = mapa_u32(h0_local, dest);
        uint32_t blk = (uint32_t)((rank * 32 + w * 4) * 4);
        peer_h[0] = base + blk;
        peer_h[1] = base + 1024u + blk;
        peer_mb[0] = mapa_u32(mb0, dest);
        peer_mb[1] = mapa_u32(mb1, dest);
    }

    cluster.sync();

    const float* gx_row = gx + (size_t)batch * Tq * G4q + row;
    const bool write_out = ((l >> 2) == rank);
    const bool sender = (l < 8);
    float c0 = 0.f;

    wait_flag(in_ready, in_target);
    float cur = gx_row[0];

    for (int t = 0; t < Tq; t++) {
        if (t + 1 < Tq && ((t + 1) & 127) == 0)
            wait_flag(in_ready + ((t + 1) >> 7), in_target);
        float nxt = 0.f;
        if (t + 1 < Tq) nxt = gx_row[(size_t)(t + 1) * G4q];

        if (t > 0) {
            const uint32_t mb = (t & 1) ? mb1 : mb0;
            unsigned par = (unsigned)(((t >> 1) + ((t & 1) ^ 1)) & 1);
            MBAR_WAIT_ACQ_CLUSTER(mb, par);
            if (tid == 0 && t + 2 < Tq) MBAR_ARM(mb, 1024);
        }
        const int p = t & 1;
        const ulonglong2* hb2 = (const ulonglong2*)(h2s + (p << 8) + (kh << 7));

        unsigned long long acc0 = 0ull, acc1 = 0ull, acc2 = 0ull, acc3 = 0ull;
#pragma unroll
        for (int i = 0; i < 32; i += 2) {
            ulonglong2 hv0 = hb2[i];
            ulonglong2 hv1 = hb2[i + 1];
            FMA_F32X2(acc0, wreg[2 * i + 0], hv0.x, acc0);
            FMA_F32X2(acc1, wreg[2 * i + 1], hv0.y, acc1);
            FMA_F32X2(acc2, wreg[2 * i + 2], hv1.x, acc2);
            FMA_F32X2(acc3, wreg[2 * i + 3], hv1.y, acc3);
        }
        float partial = (hsum_f32x2(acc0) + hsum_f32x2(acc1))
                      + (hsum_f32x2(acc2) + hsum_f32x2(acc3));
        float sum = partial + __shfl_xor_sync(0xFFFFFFFFu, partial, 16);
        sum += cur;

        float si = __shfl_sync(0xFFFFFFFFu, sum, v);
        float sf = __shfl_sync(0xFFFFFFFFu, sum, v + 4);
        float sg = __shfl_sync(0xFFFFFFFFu, sum, v + 8);
        float so = __shfl_sync(0xFFFFFFFFu, sum, v + 12);

        c0 = sigt(sf) * c0 + sigt(si) * tanha(sg);
        float hnew = sigt(so) * tanha(c0);

        if (write_out)
            h_out[((size_t)batch * Tq + t) * Hq + gunit] = hnew;

        if (t + 1 < Tq) {
            unsigned hu = __float_as_uint(hnew);
            unsigned f0 = __shfl_sync(0xFFFFFFFFu, hu, 0);
            unsigned f1 = __shfl_sync(0xFFFFFFFFu, hu, 1);
            unsigned f2 = __shfl_sync(0xFFFFFFFFu, hu, 2);
            unsigned f3 = __shfl_sync(0xFFFFFFFFu, hu, 3);
            if (sender) {
                const int q = (t + 1) & 1;
                ST_ASYNC_V4(peer_h[q], f0, f1, f2, f3, peer_mb[q]);
            }
        }

        if (out_ready && (t & 127) == 127) {
            __threadfence();
            __syncthreads();
            if (tid == 0) atomicAdd(out_ready + (t >> 7), 1);
        }
        cur = nxt;
    }
    cluster.sync();
}

// ---------------- 128x64 GEMM tile (A contiguous, SMEM from dsm) ------------
__device__ __forceinline__ void tile_128x64(
    const float* __restrict__ A, int lda, const float* __restrict__ W, int K,
    const float* __restrict__ b1, const float* __restrict__ b2,
    float* __restrict__ out, int n0, float* sA, float* sB)
{
    const int tid = threadIdx.x;
    const int tx = tid & 15, ty = tid >> 4;
    const int lmA = tid & 127, khA = (tid >> 7) * 8;
    const int lnB = tid & 63,  kB  = (tid >> 6) * 4;

    float acc[8][4];
#pragma unroll
    for (int i = 0; i < 8; i++)
#pragma unroll
        for (int j = 0; j < 4; j++) acc[i][j] = 0.f;

    for (int k0 = 0; k0 < K; k0 += 16) {
#pragma unroll
        for (int half = 0; half < 2; half++) {
            int off = khA + half * 4;
            float4 vv = *(const float4*)(A + (size_t)lmA * lda + k0 + off);
            sA[(off + 0) * 128 + lmA] = vv.x; sA[(off + 1) * 128 + lmA] = vv.y;
            sA[(off + 2) * 128 + lmA] = vv.z; sA[(off + 3) * 128 + lmA] = vv.w;
        }
        float4 wv = *(const float4*)(W + (size_t)(n0 + lnB) * K + k0 + kB);
        sB[(kB + 0) * 64 + lnB] = wv.x; sB[(kB + 1) * 64 + lnB] = wv.y;
        sB[(kB + 2) * 64 + lnB] = wv.z; sB[(kB + 3) * 64 + lnB] = wv.w;
        __syncthreads();
#pragma unroll
        for (int kk = 0; kk < 16; kk++) {
            float4 a0 = *(const float4*)&sA[kk * 128 + ty * 8];
            float4 a1 = *(const float4*)&sA[kk * 128 + ty * 8 + 4];
            float4 b  = *(const float4*)&sB[kk * 64 + tx * 4];
            float av[8] = {a0.x, a0.y, a0.z, a0.w, a1.x, a1.y, a1.z, a1.w};
#pragma unroll
            for (int i = 0; i < 8; i++) {
                acc[i][0] = fmaf(av[i], b.x, acc[i][0]);
                acc[i][1] = fmaf(av[i], b.y, acc[i][1]);
                acc[i][2] = fmaf(av[i], b.z, acc[i][2]);
                acc[i][3] = fmaf(av[i], b.w, acc[i][3]);
            }
        }
        __syncthreads();
    }

    float bias[4];
#pragma unroll
    for (int j = 0; j < 4; j++) {
        int n = n0 + tx * 4 + j;
        bias[j] = b1[n] + (b2 ? b2[n] : 0.f);
    }
#pragma unroll
    for (int i = 0; i < 8; i++) {
        float4 r = make_float4(acc[i][0] + bias[0], acc[i][1] + bias[1],
                               acc[i][2] + bias[2], acc[i][3] + bias[3]);
        *(float4*)(out + (size_t)(ty * 8 + i) * G4q + n0 + tx * 4) = r;
    }
}

// ---------------- 128x64 GEMM tile, split-K A (A1[0:Ks) | A2[Ks:K)) ---------
__device__ __forceinline__ void tile_128x64_split(
    const float* __restrict__ A1, const float* __restrict__ A2,
    int lda, int Ksplit, int K,
    const float* __restrict__ W, const float* __restrict__ b1,
    float* __restrict__ out, int n0, float* sA, float* sB)
{
    const int tid = threadIdx.x;
    const int tx = tid & 15, ty = tid >> 4;
    const int lmA = tid & 127, khA = (tid >> 7) * 8;
    const int lnB = tid & 63,  kB  = (tid >> 6) * 4;

    float acc[8][4];
#pragma unroll
    for (int i = 0; i < 8; i++)
#pragma unroll
        for (int j = 0; j < 4; j++) acc[i][j] = 0.f;

    for (int k0 = 0; k0 < K; k0 += 16) {
#pragma unroll
        for (int half = 0; half < 2; half++) {
            int off = khA + half * 4;
            int kg = k0 + off;
            float4 vv;
            if (kg < Ksplit) vv = *(const float4*)(A1 + (size_t)lmA * lda + kg);
            else             vv = *(const float4*)(A2 + (size_t)lmA * lda + (kg - Ksplit));
            sA[(off + 0) * 128 + lmA] = vv.x; sA[(off + 1) * 128 + lmA] = vv.y;
            sA[(off + 2) * 128 + lmA] = vv.z; sA[(off + 3) * 128 + lmA] = vv.w;
        }
        float4 wv = *(const float4*)(W + (size_t)(n0 + lnB) * K + k0 + kB);
        sB[(kB + 0) * 64 + lnB] = wv.x; sB[(kB + 1) * 64 + lnB] = wv.y;
        sB[(kB + 2) * 64 + lnB] = wv.z; sB[(kB + 3) * 64 + lnB] = wv.w;
        __syncthreads();
#pragma unroll
        for (int kk = 0; kk < 16; kk++) {
            float4 a0 = *(const float4*)&sA[kk * 128 + ty * 8];
            float4 a1 = *(const float4*)&sA[kk * 128 + ty * 8 + 4];
            float4 b  = *(const float4*)&sB[kk * 64 + tx * 4];
            float av[8] = {a0.x, a0.y, a0.z, a0.w, a1.x, a1.y, a1.z, a1.w};
#pragma unroll
            for (int i = 0; i < 8; i++) {
                acc[i][0] = fmaf(av[i], b.x, acc[i][0]);
                acc[i][1] = fmaf(av[i], b.y, acc[i][1]);
                acc[i][2] = fmaf(av[i], b.z, acc[i][2]);
                acc[i][3] = fmaf(av[i], b.w, acc[i][3]);
            }
        }
        __syncthreads();
    }

    float bias[4];
#pragma unroll
    for (int j = 0; j < 4; j++) bias[j] = b1[n0 + tx * 4 + j];
#pragma unroll
    for (int i = 0; i < 8; i++) {
        float4 r = make_float4(acc[i][0] + bias[0], acc[i][1] + bias[1],
                               acc[i][2] + bias[2], acc[i][3] + bias[3]);
        *(float4*)(out + (size_t)(ty * 8 + i) * G4q + n0 + tx * 4) = r;
    }
}

// ---------------- chunked gx gemm role ----------------
__device__ __forceinline__ void gemm_chunk_role(
    const float* __restrict__ A0, int lda, const float* __restrict__ W,
    const float* __restrict__ b1, const float* __restrict__ b2,
    float* __restrict__ out0, int K, int slice_n0,
    volatile int* in_ready, int in_target, int* out_ready, float* dsm)
{
    float* sA = dsm;
    float* sB = dsm + 2048;
    for (int c = 0; c < 16; c++) {
        if (in_ready) wait_flag(in_ready + c, in_target);
        const float* A = A0 + (size_t)c * 128 * lda;
        float* out = out0 + (size_t)c * 128 * G4q;
        for (int j = 0; j < 4; j++)
            tile_128x64(A, lda, W, K, b1, b2, out, slice_n0 + j * 64, sA, sB);
        __threadfence();
        __syncthreads();
        if (threadIdx.x == 0) atomicAdd(out_ready + c, 1);
    }
}

// ---------------- chunked kv gemm role (trails scan1; cv ready pre-launch) ---
__device__ __forceinline__ void kv_role(
    const float* __restrict__ h2, const float* __restrict__ cv,
    const float* __restrict__ qkv_w, const float* __restrict__ qkv_b,
    float* __restrict__ kvout, int b, int slice_n0, float* dsm)
{
    float* sA = dsm;
    float* sB = dsm + 2048;
    volatile int* h2f = (volatile int*)&g_flags[3][b][0];
    for (int c = 0; c < 16; c++) {
        wait_flag(h2f + c, 8);
        const float* A1 = h2 + (size_t)(b * Tq + c * 128) * Hq;
        const float* A2 = cv + (size_t)(b * Tq + c * 128) * Hq;
        float* out = kvout + (size_t)(b * Tq + c * 128) * G4q;
        for (int j = 0; j < 2; j++)
            tile_128x64_split(A1, A2, Hq, 256, 512,
                              qkv_w + 512 * 512, qkv_b + 512,
                              out, slice_n0 + j * 64, sA, sB);
    }
}

// ---------------- mega kernel ----------------
// grid = 128 CTAs (16 clusters x 8), 1 CTA/SM -> all co-resident.
// 0-31: layer-0 scan; 32-63: layer-1 scan (publishes h2 chunks);
// 64-79: gx1 gemm; 80-95: gx0 gemm; 96-127: kv gemm (8 CTAs/batch).
__global__ void __cluster_dims__(8, 1, 1) __launch_bounds__(256, 1) mega(
    const float* __restrict__ x,
    const float* __restrict__ wih0, const float* __restrict__ whh0,
    const float* __restrict__ bih0, const float* __restrict__ bhh0,
    const float* __restrict__ wih1, const float* __restrict__ whh1,
    const float* __restrict__ bih1, const float* __restrict__ bhh1,
    const float* __restrict__ qkvw, const float* __restrict__ qkvb,
    float* __restrict__ gx0, float* __restrict__ gx1,
    float* __restrict__ h1, float* __restrict__ h2, float* __restrict__ kv)
{
    extern __shared__ float dsm[];
    const int cid = blockIdx.x >> 3;

    if (cid < 4) {
        scan_role(gx0, whh0, h1, cid,
                  (volatile int*)&g_flags[0][cid][0], 4,
                  &g_flags[1][cid][0], dsm);
    } else if (cid < 8) {
        scan_role(gx1, whh1, h2, cid - 4,
                  (volatile int*)&g_flags[2][cid - 4][0], 4,
                  &g_flags[3][cid - 4][0], dsm);
    } else if (blockIdx.x < 80) {
        const int idx = blockIdx.x - 64;
        const int b = idx & 3, slice = idx >> 2;
        gemm_chunk_role(h1 + (size_t)b * Tq * Hq, Hq, wih1, bih1, bhh1,
                        gx1 + (size_t)b * Tq * G4q, Hq, slice * 256,
                        (volatile int*)&g_flags[1][b][0], 8,
                        &g_flags[2][b][0], dsm);
    } else if (blockIdx.x < 96) {
        const int idx = blockIdx.x - 80;
        const int b = idx & 3, slice = idx >> 2;
        gemm_chunk_role(x + (size_t)b * Tq * INq, INq, wih0, bih0, bhh0,
                        gx0 + (size_t)b * Tq * G4q, INq, slice * 256,
                        nullptr, 0,
                        &g_flags[0][b][0], dsm);
    } else {
        const int idx = blockIdx.x - 96;            // 0..31
        const int b = idx >> 3, slice = idx & 7;    // 8 slices x 128 cols
        kv_role(h2, g_cv, qkvw, qkvb, kv, b, slice * 128, dsm);
    }
}

// ---------------- flag reset (graph-replay determinism) ----------------
__global__ void reset_flags() {
    ((int*)g_flags)[threadIdx.x] = 0;
}

// ---------------- conv1d(K=5,same) + BN + SiLU (full-chip, pre-mega) ---------
__global__ __launch_bounds__(256, 1) void conv_bn_silu(
    const float* __restrict__ x, const float* __restrict__ cw,
    const float* __restrict__ cb, const float* __restrict__ bg,
    const float* __restrict__ bnb, const float* __restrict__ bmean,
    const float* __restrict__ bvar)
{
    extern __shared__ float sm[];
    float* xs = sm;              // [36][64]
    float* ws = sm + 36 * 64;    // [64][321]
    const int b = blockIdx.z;
    const int t0 = blockIdx.x * 32;
    const int ocb = blockIdx.y * 64;
    const int tid = threadIdx.x;

    for (int idx = tid; idx < 36 * 64; idx += 256) {
        int tr = idx >> 6, i = idx & 63;
        int tg = t0 + tr - 2;
        xs[idx] = (tg >= 0 && tg < Tq) ? x[((size_t)b * Tq + tg) * INq + i] : 0.f;
    }
    for (int idx = tid; idx < 64 * 320; idx += 256) {
        int o = idx / 320, ik = idx % 320;
        ws[o * 321 + ik] = cw[(size_t)(ocb + o) * 320 + ik];
    }
    __syncthreads();

    const int o = tid & 63, gq = tid >> 6;
    const int tb = gq * 8;
    float acc[8];
#pragma unroll
    for (int t = 0; t < 8; t++) acc[t] = 0.f;

    for (int i = 0; i < 64; i++) {
        float xv[12];
#pragma unroll
        for (int j = 0; j < 12; j++) xv[j] = xs[(tb + j) * 64 + i];
#pragma unroll
        for (int k = 0; k < 5; k++) {
            float wv = ws[o * 321 + i * 5 + k];
#pragma unroll
            for (int t = 0; t < 8; t++) acc[t] = fmaf(xv[t + k], wv, acc[t]);
        }
    }
    const int oc = ocb + o;
    float scl = rsqrtf(bvar[oc] + EPSq) * bg[oc];
    float sh = bnb[oc] - bmean[oc] * scl;
    float cbv = cb[oc];
#pragma unroll
    for (int t = 0; t < 8; t++) {
        float y = (acc[t] + cbv) * scl + sh;
        g_cv[((size_t)b * Tq + t0 + tb + t) * Hq + oc] = y / (1.f + __expf(-y));
    }
}

// ---------------- attention (last query row only) ----------------
__global__ __launch_bounds__(256) void attn_last(
    const float* __restrict__ qkv_w, const float* __restrict__ qkv_b)
{
    __shared__ float q[64];
    __shared__ float sc[Tq];
    __shared__ float red[256];
    __shared__ float vp[256];
    const int bh = blockIdx.x;
    const int b = bh >> 3, h = bh & 7;
    const int tid = threadIdx.x;

    if (tid < 64) {
        int row = h * 64 + tid;
        const float* wr = qkv_w + (size_t)row * Dq;
        const float* ml = g_h2 + ((size_t)b * Tq + (Tq - 1)) * Hq;
        const float* mc = g_cv + ((size_t)b * Tq + (Tq - 1)) * Hq;
        float acc = qkv_b[row];
        for (int k = 0; k < 256; k++) acc = fmaf(ml[k], wr[k], acc);
        for (int k = 0; k < 256; k++) acc = fmaf(mc[k], wr[256 + k], acc);
        q[tid] = acc * 0.125f;
    }
    __syncthreads();

    float lmax = -1e30f;
    for (int t = tid; t < Tq; t += 256) {
        const float4* kp = (const float4*)(g_kv + ((size_t)b * Tq + t) * G4q + h * 64);
        float s = 0.f;
#pragma unroll
        for (int d4 = 0; d4 < 16; d4++) {
            float4 kk = kp[d4];
            float4 qq = ((const float4*)q)[d4];
            s += kk.x * qq.x + kk.y * qq.y + kk.z * qq.z + kk.w * qq.w;
        }
        sc[t] = s;
        lmax = fmaxf(lmax, s);
    }
    red[tid] = lmax; __syncthreads();
    for (int s2 = 128; s2 > 0; s2 >>= 1) {
        if (tid < s2) red[tid] = fmaxf(red[tid], red[tid + s2]);
        __syncthreads();
    }
    float m = red[0];
    __syncthreads();

    float lsum = 0.f;
    for (int t = tid; t < Tq; t += 256) {
        float pe = __expf(sc[t] - m);
        sc[t] = pe;
        lsum += pe;
    }
    red[tid] = lsum; __syncthreads();
    for (int s2 = 128; s2 > 0; s2 >>= 1) {
        if (tid < s2) red[tid] += red[tid + s2];
        __syncthreads();
    }
    float denom = red[0];
    __syncthreads();

    const int d = tid & 63, gg = tid >> 6;
    float acc = 0.f;
    for (int t = gg * 512; t < (gg + 1) * 512; t++)
        acc = fmaf(sc[t], g_kv[((size_t)b * Tq + t) * G4q + 512 + h * 64 + d], acc);
    vp[tid] = acc; __syncthreads();
    if (tid < 64) {
        float o = (vp[tid] + vp[64 + tid] + vp[128 + tid] + vp[192 + tid]) / denom;
        g_at[b * Dq + h * 64 + tid] = o;
    }
}

// ---------------- head ----------------
__global__ __launch_bounds__(512) void head_kernel(
    const float* __restrict__ pw, const float* __restrict__ pb,
    const float* __restrict__ lng, const float* __restrict__ lnb,
    const float* __restrict__ f1w, const float* __restrict__ f1b,
    const float* __restrict__ f2w, const float* __restrict__ f2b,
    float* __restrict__ out)
{
    __shared__ float a[Dq], zn[Dq], z2[Hq], red[512];
    const int b = blockIdx.x, tid = threadIdx.x;
    a[tid] = g_at[b * Dq + tid];
    __syncthreads();

    float acc = pb[tid];
    const float* wr = pw + (size_t)tid * Dq;
    for (int k = 0; k < Dq; k++) acc = fmaf(a[k], wr[k], acc);
    float mrg = (tid < 256) ? g_h2[((size_t)b * Tq + Tq - 1) * Hq + tid]
                            : g_cv[((size_t)b * Tq + Tq - 1) * Hq + tid - 256];
    float z = acc + mrg;

    red[tid] = z; __syncthreads();
    for (int s = 256; s > 0; s >>= 1) {
        if (tid < s) red[tid] += red[tid + s];
        __syncthreads();
    }
    float mu = red[0] / 512.f;
    __syncthreads();
    float dv = z - mu;
    red[tid] = dv * dv; __syncthreads();
    for (int s = 256; s > 0; s >>= 1) {
        if (tid < s) red[tid] += red[tid + s];
        __syncthreads();
    }
    float var = red[0] / 512.f;
    __syncthreads();

    zn[tid] = dv * rsqrtf(var + EPSq) * lng[tid] + lnb[tid];
    __syncthreads();

    if (tid < 256) {
        float a2 = f1b[tid];
        const float* w1 = f1w + (size_t)tid * Dq;
        for (int k = 0; k < Dq; k++) a2 = fmaf(zn[k], w1[k], a2);
        z2[tid] = a2 / (1.f + expf(-a2));
    }
    __syncthreads();

    if (tid < 3) {
        float lg = f2b[tid];
        const float* w2 = f2w + tid * 256;
        for (int j = 0; j < 256; j++) lg = fmaf(z2[j], w2[j], lg);
        if (tid == 0)      out[b]     = tanhf(lg);
        else if (tid == 1) out[4 + b] = (lg > 20.f) ? lg : log1pf(expf(lg));
        else               out[8 + b] = 1.f / (1.f + expf(-lg));
    }
}

// ---------------- launch ----------------
extern "C" void kernel_launch(void* const* d_in, const int* in_sizes, int n_in,
                              void* d_out, int out_size) {
    const float* x     = (const float*)d_in[0];
    const float* wih0  = (const float*)d_in[1];
    const float* whh0  = (const float*)d_in[2];
    const float* bih0  = (const float*)d_in[3];
    const float* bhh0  = (const float*)d_in[4];
    const float* wih1  = (const float*)d_in[5];
    const float* whh1  = (const float*)d_in[6];
    const float* bih1  = (const float*)d_in[7];
    const float* bhh1  = (const float*)d_in[8];
    const float* cw    = (const float*)d_in[9];
    const float* cb    = (const float*)d_in[10];
    const float* bng   = (const float*)d_in[11];
    const float* bnb   = (const float*)d_in[12];
    const float* bnm   = (const float*)d_in[13];
    const float* bnv   = (const float*)d_in[14];
    const float* qkvw  = (const float*)d_in[15];
    const float* qkvb  = (const float*)d_in[16];
    const float* pw    = (const float*)d_in[17];
    const float* pbv   = (const float*)d_in[18];
    const float* lng   = (const float*)d_in[19];
    const float* lnb   = (const float*)d_in[20];
    const float* f1w   = (const float*)d_in[21];
    const float* f1b   = (const float*)d_in[22];
    const float* f2w   = (const float*)d_in[23];
    const float* f2b   = (const float*)d_in[24];
    float* out = (float*)d_out;

    float *gx0, *gx1, *h1, *h2, *kv;
    cudaGetSymbolAddress((void**)&gx0, g_gx0);
    cudaGetSymbolAddress((void**)&gx1, g_gx1);
    cudaGetSymbolAddress((void**)&h1,  g_h1);
    cudaGetSymbolAddress((void**)&h2,  g_h2);
    cudaGetSymbolAddress((void**)&kv,  g_kv);

    const int conv_smem = (36 * 64 + 64 * 321) * 4;
    const int mega_smem = (2048 + 1024) * 4;   // 12 KB
    cudaFuncSetAttribute(conv_bn_silu, cudaFuncAttributeMaxDynamicSharedMemorySize, conv_smem);

    // 0: reset chunk flags (graph-replay determinism)
    reset_flags<<<1, 256>>>();
    // 1: conv branch (full-chip, completes before mega; kv role reads g_cv)
    conv_bn_silu<<<dim3(64, 4, 4), 256, conv_smem>>>(x, cw, cb, bng, bnb, bnm, bnv);
    // 2: fused pipeline: gx0 -> scan0 -> gx1 -> scan1 -> kv, chunk-overlapped
    mega<<<128, 256, mega_smem>>>(x, wih0, whh0, bih0, bhh0,
                                  wih1, whh1, bih1, bhh1,
                                  qkvw, qkvb,
                                  gx0, gx1, h1, h2, kv);
    // 3: attention (last row only)
    attn_last<<<32, 256>>>(qkvw, qkvb);
    // 4: head
    head_kernel<<<4, 512>>>(pw, pbv, lng, lnb, f1w, f1b, f2w, f2b, out);
}

// round 16
// speedup vs baseline: 1.7649x; 1.0861x over previous
#include <cuda_runtime.h>
#include <cooperative_groups.h>
#include <math.h>

namespace cg = cooperative_groups;

#define Bq   4
#define Tq   2048
#define INq  64
#define Hq   256
#define Dq   512
#define G4q  1024
#define EPSq 1e-5f

// ---------------- static scratch ----------------
__device__ float g_gx0[Bq * Tq * G4q];
__device__ float g_gx1[Bq * Tq * G4q];
__device__ float g_h1 [Bq * Tq * Hq];
__device__ float g_h2 [Bq * Tq * Hq];
__device__ float g_cv [Bq * Tq * Hq];
__device__ float g_kv [Bq * Tq * G4q];
__device__ float g_at [Bq * Dq];
__device__ float g_q  [Bq * Dq];
__device__ float g_part[Bq * 8 * 8 * 66];   // [b][h][seg]{m, s, u[64]}

// chunk-ready flags: [0]=gx0(target4) [1]=h1(target8) [2]=gx1(target4) [3]=h2(target8)
__device__ int g_flags[4][Bq][16];

#define FMA_F32X2(d, a, b, c) \
    asm("fma.rn.f32x2 %0, %1, %2, %3;" : "=l"(d) : "l"(a), "l"(b), "l"(c))

__device__ __forceinline__ float hsum_f32x2(unsigned long long v) {
    float lo, hi;
    asm("mov.b64 {%0, %1}, %2;" : "=f"(lo), "=f"(hi) : "l"(v));
    return lo + hi;
}
__device__ __forceinline__ float tanha(float x) {
    float y; asm("tanh.approx.f32 %0, %1;" : "=f"(y) : "f"(x)); return y;
}
__device__ __forceinline__ float sigt(float x) {
    return fmaf(0.5f, tanha(0.5f * x), 0.5f);
}

// ---------------- mbarrier / st.async helpers ----------------
#define MBAR_WAIT_ACQ_CLUSTER(addr, par) do {                                    \
    unsigned _done;                                                              \
    asm volatile("{\n\t.reg .pred P;\n\t"                                        \
        "mbarrier.try_wait.parity.acquire.cluster.shared::cta.b64 P, [%1], %2;\n\t" \
        "selp.b32 %0, 1, 0, P;\n\t}"                                             \
        : "=r"(_done) : "r"(addr), "r"(par) : "memory");                         \
    while (!_done) {                                                             \
        asm volatile("{\n\t.reg .pred P;\n\t"                                    \
            "mbarrier.try_wait.parity.acquire.cluster.shared::cta.b64 P, [%1], %2, 0x989680;\n\t" \
            "selp.b32 %0, 1, 0, P;\n\t}"                                         \
            : "=r"(_done) : "r"(addr), "r"(par) : "memory");                     \
    }                                                                            \
} while (0)

#define MBAR_ARM(addr, bytes) \
    asm volatile("mbarrier.arrive.expect_tx.shared.b64 _, [%0], %1;"             \
                 :: "r"(addr), "r"(bytes) : "memory")

#define ST_ASYNC_V4(daddr, r0, r1, r2, r3, mbaraddr) \
    asm volatile("st.async.weak.shared::cluster.mbarrier::complete_tx::bytes.v4.b32 " \
                 "[%0], {%1, %2, %3, %4}, [%5];"                                 \
                 :: "r"(daddr), "r"(r0), "r"(r1), "r"(r2), "r"(r3),              \
                    "r"(mbaraddr) : "memory")

__device__ __forceinline__ uint32_t smem_u32(const void* p) {
    uint32_t a;
    asm("{ .reg .u64 t; cvta.to.shared.u64 t, %1; cvt.u32.u64 %0, t; }"
        : "=r"(a) : "l"(p));
    return a;
}
__device__ __forceinline__ uint32_t mapa_u32(uint32_t a, int r) {
    uint32_t o;
    asm("mapa.shared::cluster.u32 %0, %1, %2;" : "=r"(o) : "r"(a), "r"(r));
    return o;
}

__device__ __forceinline__ void wait_flag(volatile int* f, int target) {
    if (*f < target) { while (*f < target) {} }
    __threadfence();
}

__device__ __forceinline__ float warp_sum(float v) {
#pragma unroll
    for (int o = 16; o > 0; o >>= 1) v += __shfl_xor_sync(0xFFFFFFFFu, v, o);
    return v;
}

// ---------------- scan role (R8-proven structure + chunk gating) ----------------
__device__ __forceinline__ void scan_role(
    const float* __restrict__ gx, const float* __restrict__ w_hh,
    float* __restrict__ h_out, int batch,
    volatile int* in_ready, int in_target, int* out_ready, float* dsm)
{
    float* h2s = dsm;                                     // [2][256]
    unsigned long long* mbars = (unsigned long long*)(dsm + 512);

    cg::cluster_group cluster = cg::this_cluster();
    const int rank = (int)cluster.block_rank();
    const int tid = threadIdx.x;
    const int w = tid >> 5, l = tid & 31;
    const int v  = l & 3;
    const int g  = (l >> 2) & 3;
    const int kh = l >> 4;
    const int gunit = rank * 32 + w * 4 + v;
    const int row = g * Hq + gunit;

    unsigned long long wreg[64];
    {
        const ulonglong2* wp = (const ulonglong2*)(w_hh + (size_t)row * Hq + (kh << 7));
#pragma unroll
        for (int i = 0; i < 32; i++) {
            ulonglong2 t2 = wp[i];
            wreg[2 * i]     = t2.x;
            wreg[2 * i + 1] = t2.y;
        }
    }

    if (tid < 256) { h2s[tid] = 0.f; h2s[256 + tid] = 0.f; }

    const uint32_t mb0 = smem_u32(&mbars[0]);
    const uint32_t mb1 = smem_u32(&mbars[1]);
    if (tid == 0) {
        asm volatile("mbarrier.init.shared.b64 [%0], 1;" :: "r"(mb0) : "memory");
        asm volatile("mbarrier.init.shared.b64 [%0], 1;" :: "r"(mb1) : "memory");
        MBAR_ARM(mb1, 1024);
        MBAR_ARM(mb0, 1024);
    }

    const uint32_t h0_local = smem_u32(&h2s[0]);
    const int dest = l & 7;
    uint32_t peer_h[2], peer_mb[2];
    {
        uint32_t base = mapa_u32(h0_local, dest);
        uint32_t blk = (uint32_t)((rank * 32 + w * 4) * 4);
        peer_h[0] = base + blk;
        peer_h[1] = base + 1024u + blk;
        peer_mb[0] = mapa_u32(mb0, dest);
        peer_mb[1] = mapa_u32(mb1, dest);
    }

    cluster.sync();

    const float* gx_row = gx + (size_t)batch * Tq * G4q + row;
    const bool write_out = ((l >> 2) == rank);
    const bool sender = (l < 8);
    float c0 = 0.f;

    wait_flag(in_ready, in_target);
    float cur = gx_row[0];

    for (int t = 0; t < Tq; t++) {
        if (t + 1 < Tq && ((t + 1) & 127) == 0)
            wait_flag(in_ready + ((t + 1) >> 7), in_target);
        float nxt = 0.f;
        if (t + 1 < Tq) nxt = gx_row[(size_t)(t + 1) * G4q];

        if (t > 0) {
            const uint32_t mb = (t & 1) ? mb1 : mb0;
            unsigned par = (unsigned)(((t >> 1) + ((t & 1) ^ 1)) & 1);
            MBAR_WAIT_ACQ_CLUSTER(mb, par);
            if (tid == 0 && t + 2 < Tq) MBAR_ARM(mb, 1024);
        }
        const int p = t & 1;
        const ulonglong2* hb2 = (const ulonglong2*)(h2s + (p << 8) + (kh << 7));

        unsigned long long acc0 = 0ull, acc1 = 0ull, acc2 = 0ull, acc3 = 0ull;
#pragma unroll
        for (int i = 0; i < 32; i += 2) {
            ulonglong2 hv0 = hb2[i];
            ulonglong2 hv1 = hb2[i + 1];
            FMA_F32X2(acc0, wreg[2 * i + 0], hv0.x, acc0);
            FMA_F32X2(acc1, wreg[2 * i + 1], hv0.y, acc1);
            FMA_F32X2(acc2, wreg[2 * i + 2], hv1.x, acc2);
            FMA_F32X2(acc3, wreg[2 * i + 3], hv1.y, acc3);
        }
        float partial = (hsum_f32x2(acc0) + hsum_f32x2(acc1))
                      + (hsum_f32x2(acc2) + hsum_f32x2(acc3));
        float sum = partial + __shfl_xor_sync(0xFFFFFFFFu, partial, 16);
        sum += cur;

        float si = __shfl_sync(0xFFFFFFFFu, sum, v);
        float sf = __shfl_sync(0xFFFFFFFFu, sum, v + 4);
        float sg = __shfl_sync(0xFFFFFFFFu, sum, v + 8);
        float so = __shfl_sync(0xFFFFFFFFu, sum, v + 12);

        c0 = sigt(sf) * c0 + sigt(si) * tanha(sg);
        float hnew = sigt(so) * tanha(c0);

        if (write_out)
            h_out[((size_t)batch * Tq + t) * Hq + gunit] = hnew;

        if (t + 1 < Tq) {
            unsigned hu = __float_as_uint(hnew);
            unsigned f0 = __shfl_sync(0xFFFFFFFFu, hu, 0);
            unsigned f1 = __shfl_sync(0xFFFFFFFFu, hu, 1);
            unsigned f2 = __shfl_sync(0xFFFFFFFFu, hu, 2);
            unsigned f3 = __shfl_sync(0xFFFFFFFFu, hu, 3);
            if (sender) {
                const int q = (t + 1) & 1;
                ST_ASYNC_V4(peer_h[q], f0, f1, f2, f3, peer_mb[q]);
            }
        }

        if (out_ready && (t & 127) == 127) {
            __threadfence();
            __syncthreads();
            if (tid == 0) atomicAdd(out_ready + (t >> 7), 1);
        }
        cur = nxt;
    }
    cluster.sync();
}

// ---------------- 128x64 GEMM tile (A contiguous, SMEM from dsm) ------------
__device__ __forceinline__ void tile_128x64(
    const float* __restrict__ A, int lda, const float* __restrict__ W, int K,
    const float* __restrict__ b1, const float* __restrict__ b2,
    float* __restrict__ out, int n0, float* sA, float* sB)
{
    const int tid = threadIdx.x;
    const int tx = tid & 15, ty = tid >> 4;
    const int lmA = tid & 127, khA = (tid >> 7) * 8;
    const int lnB = tid & 63,  kB  = (tid >> 6) * 4;

    float acc[8][4];
#pragma unroll
    for (int i = 0; i < 8; i++)
#pragma unroll
        for (int j = 0; j < 4; j++) acc[i][j] = 0.f;

    for (int k0 = 0; k0 < K; k0 += 16) {
#pragma unroll
        for (int half = 0; half < 2; half++) {
            int off = khA + half * 4;
            float4 vv = *(const float4*)(A + (size_t)lmA * lda + k0 + off);
            sA[(off + 0) * 128 + lmA] = vv.x; sA[(off + 1) * 128 + lmA] = vv.y;
            sA[(off + 2) * 128 + lmA] = vv.z; sA[(off + 3) * 128 + lmA] = vv.w;
        }
        float4 wv = *(const float4*)(W + (size_t)(n0 + lnB) * K + k0 + kB);
        sB[(kB + 0) * 64 + lnB] = wv.x; sB[(kB + 1) * 64 + lnB] = wv.y;
        sB[(kB + 2) * 64 + lnB] = wv.z; sB[(kB + 3) * 64 + lnB] = wv.w;
        __syncthreads();
#pragma unroll
        for (int kk = 0; kk < 16; kk++) {
            float4 a0 = *(const float4*)&sA[kk * 128 + ty * 8];
            float4 a1 = *(const float4*)&sA[kk * 128 + ty * 8 + 4];
            float4 b  = *(const float4*)&sB[kk * 64 + tx * 4];
            float av[8] = {a0.x, a0.y, a0.z, a0.w, a1.x, a1.y, a1.z, a1.w};
#pragma unroll
            for (int i = 0; i < 8; i++) {
                acc[i][0] = fmaf(av[i], b.x, acc[i][0]);
                acc[i][1] = fmaf(av[i], b.y, acc[i][1]);
                acc[i][2] = fmaf(av[i], b.z, acc[i][2]);
                acc[i][3] = fmaf(av[i], b.w, acc[i][3]);
            }
        }
        __syncthreads();
    }

    float bias[4];
#pragma unroll
    for (int j = 0; j < 4; j++) {
        int n = n0 + tx * 4 + j;
        bias[j] = b1[n] + (b2 ? b2[n] : 0.f);
    }
#pragma unroll
    for (int i = 0; i < 8; i++) {
        float4 r = make_float4(acc[i][0] + bias[0], acc[i][1] + bias[1],
                               acc[i][2] + bias[2], acc[i][3] + bias[3]);
        *(float4*)(out + (size_t)(ty * 8 + i) * G4q + n0 + tx * 4) = r;
    }
}

// ---------------- 128x64 GEMM tile, split-K A (A1[0:Ks) | A2[Ks:K)) ---------
__device__ __forceinline__ void tile_128x64_split(
    const float* __restrict__ A1, const float* __restrict__ A2,
    int lda, int Ksplit, int K,
    const float* __restrict__ W, const float* __restrict__ b1,
    float* __restrict__ out, int n0, float* sA, float* sB)
{
    const int tid = threadIdx.x;
    const int tx = tid & 15, ty = tid >> 4;
    const int lmA = tid & 127, khA = (tid >> 7) * 8;
    const int lnB = tid & 63,  kB  = (tid >> 6) * 4;

    float acc[8][4];
#pragma unroll
    for (int i = 0; i < 8; i++)
#pragma unroll
        for (int j = 0; j < 4; j++) acc[i][j] = 0.f;

    for (int k0 = 0; k0 < K; k0 += 16) {
#pragma unroll
        for (int half = 0; half < 2; half++) {
            int off = khA + half * 4;
            int kg = k0 + off;
            float4 vv;
            if (kg < Ksplit) vv = *(const float4*)(A1 + (size_t)lmA * lda + kg);
            else             vv = *(const float4*)(A2 + (size_t)lmA * lda + (kg - Ksplit));
            sA[(off + 0) * 128 + lmA] = vv.x; sA[(off + 1) * 128 + lmA] = vv.y;
            sA[(off + 2) * 128 + lmA] = vv.z; sA[(off + 3) * 128 + lmA] = vv.w;
        }
        float4 wv = *(const float4*)(W + (size_t)(n0 + lnB) * K + k0 + kB);
        sB[(kB + 0) * 64 + lnB] = wv.x; sB[(kB + 1) * 64 + lnB] = wv.y;
        sB[(kB + 2) * 64 + lnB] = wv.z; sB[(kB + 3) * 64 + lnB] = wv.w;
        __syncthreads();
#pragma unroll
        for (int kk = 0; kk < 16; kk++) {
            float4 a0 = *(const float4*)&sA[kk * 128 + ty * 8];
            float4 a1 = *(const float4*)&sA[kk * 128 + ty * 8 + 4];
            float4 b  = *(const float4*)&sB[kk * 64 + tx * 4];
            float av[8] = {a0.x, a0.y, a0.z, a0.w, a1.x, a1.y, a1.z, a1.w};
#pragma unroll
            for (int i = 0; i < 8; i++) {
                acc[i][0] = fmaf(av[i], b.x, acc[i][0]);
                acc[i][1] = fmaf(av[i], b.y, acc[i][1]);
                acc[i][2] = fmaf(av[i], b.z, acc[i][2]);
                acc[i][3] = fmaf(av[i], b.w, acc[i][3]);
            }
        }
        __syncthreads();
    }

    float bias[4];
#pragma unroll
    for (int j = 0; j < 4; j++) bias[j] = b1[n0 + tx * 4 + j];
#pragma unroll
    for (int i = 0; i < 8; i++) {
        float4 r = make_float4(acc[i][0] + bias[0], acc[i][1] + bias[1],
                               acc[i][2] + bias[2], acc[i][3] + bias[3]);
        *(float4*)(out + (size_t)(ty * 8 + i) * G4q + n0 + tx * 4) = r;
    }
}

// ---------------- chunked gx gemm role ----------------
__device__ __forceinline__ void gemm_chunk_role(
    const float* __restrict__ A0, int lda, const float* __restrict__ W,
    const float* __restrict__ b1, const float* __restrict__ b2,
    float* __restrict__ out0, int K, int slice_n0,
    volatile int* in_ready, int in_target, int* out_ready, float* dsm)
{
    float* sA = dsm;
    float* sB = dsm + 2048;
    for (int c = 0; c < 16; c++) {
        if (in_ready) wait_flag(in_ready + c, in_target);
        const float* A = A0 + (size_t)c * 128 * lda;
        float* out = out0 + (size_t)c * 128 * G4q;
        for (int j = 0; j < 4; j++)
            tile_128x64(A, lda, W, K, b1, b2, out, slice_n0 + j * 64, sA, sB);
        __threadfence();
        __syncthreads();
        if (threadIdx.x == 0) atomicAdd(out_ready + c, 1);
    }
}

// ---------------- chunked kv gemm role (trails scan1; cv ready pre-launch) ---
__device__ __forceinline__ void kv_role(
    const float* __restrict__ h2, const float* __restrict__ cv,
    const float* __restrict__ qkv_w, const float* __restrict__ qkv_b,
    float* __restrict__ kvout, int b, int slice_n0, float* dsm)
{
    float* sA = dsm;
    float* sB = dsm + 2048;
    volatile int* h2f = (volatile int*)&g_flags[3][b][0];
    for (int c = 0; c < 16; c++) {
        wait_flag(h2f + c, 8);
        const float* A1 = h2 + (size_t)(b * Tq + c * 128) * Hq;
        const float* A2 = cv + (size_t)(b * Tq + c * 128) * Hq;
        float* out = kvout + (size_t)(b * Tq + c * 128) * G4q;
        for (int j = 0; j < 2; j++)
            tile_128x64_split(A1, A2, Hq, 256, 512,
                              qkv_w + 512 * 512, qkv_b + 512,
                              out, slice_n0 + j * 64, sA, sB);
    }
}

// ---------------- mega kernel ----------------
__global__ void __cluster_dims__(8, 1, 1) __launch_bounds__(256, 1) mega(
    const float* __restrict__ x,
    const float* __restrict__ wih0, const float* __restrict__ whh0,
    const float* __restrict__ bih0, const float* __restrict__ bhh0,
    const float* __restrict__ wih1, const float* __restrict__ whh1,
    const float* __restrict__ bih1, const float* __restrict__ bhh1,
    const float* __restrict__ qkvw, const float* __restrict__ qkvb,
    float* __restrict__ gx0, float* __restrict__ gx1,
    float* __restrict__ h1, float* __restrict__ h2, float* __restrict__ kv)
{
    extern __shared__ float dsm[];
    const int cid = blockIdx.x >> 3;

    if (cid < 4) {
        scan_role(gx0, whh0, h1, cid,
                  (volatile int*)&g_flags[0][cid][0], 4,
                  &g_flags[1][cid][0], dsm);
    } else if (cid < 8) {
        scan_role(gx1, whh1, h2, cid - 4,
                  (volatile int*)&g_flags[2][cid - 4][0], 4,
                  &g_flags[3][cid - 4][0], dsm);
    } else if (blockIdx.x < 80) {
        const int idx = blockIdx.x - 64;
        const int b = idx & 3, slice = idx >> 2;
        gemm_chunk_role(h1 + (size_t)b * Tq * Hq, Hq, wih1, bih1, bhh1,
                        gx1 + (size_t)b * Tq * G4q, Hq, slice * 256,
                        (volatile int*)&g_flags[1][b][0], 8,
                        &g_flags[2][b][0], dsm);
    } else if (blockIdx.x < 96) {
        const int idx = blockIdx.x - 80;
        const int b = idx & 3, slice = idx >> 2;
        gemm_chunk_role(x + (size_t)b * Tq * INq, INq, wih0, bih0, bhh0,
                        gx0 + (size_t)b * Tq * G4q, INq, slice * 256,
                        nullptr, 0,
                        &g_flags[0][b][0], dsm);
    } else {
        const int idx = blockIdx.x - 96;
        const int b = idx >> 3, slice = idx & 7;
        kv_role(h2, g_cv, qkvw, qkvb, kv, b, slice * 128, dsm);
    }
}

// ---------------- flag reset (graph-replay determinism) ----------------
__global__ void reset_flags() {
    ((int*)g_flags)[threadIdx.x] = 0;
}

// ---------------- conv1d(K=5,same) + BN + SiLU (full-chip, pre-mega) ---------
__global__ __launch_bounds__(256, 1) void conv_bn_silu(
    const float* __restrict__ x, const float* __restrict__ cw,
    const float* __restrict__ cb, const float* __restrict__ bg,
    const float* __restrict__ bnb, const float* __restrict__ bmean,
    const float* __restrict__ bvar)
{
    extern __shared__ float sm[];
    float* xs = sm;              // [36][64]
    float* ws = sm + 36 * 64;    // [64][321]
    const int b = blockIdx.z;
    const int t0 = blockIdx.x * 32;
    const int ocb = blockIdx.y * 64;
    const int tid = threadIdx.x;

    for (int idx = tid; idx < 36 * 64; idx += 256) {
        int tr = idx >> 6, i = idx & 63;
        int tg = t0 + tr - 2;
        xs[idx] = (tg >= 0 && tg < Tq) ? x[((size_t)b * Tq + tg) * INq + i] : 0.f;
    }
    for (int idx = tid; idx < 64 * 320; idx += 256) {
        int o = idx / 320, ik = idx % 320;
        ws[o * 321 + ik] = cw[(size_t)(ocb + o) * 320 + ik];
    }
    __syncthreads();

    const int o = tid & 63, gq = tid >> 6;
    const int tb = gq * 8;
    float acc[8];
#pragma unroll
    for (int t = 0; t < 8; t++) acc[t] = 0.f;

    for (int i = 0; i < 64; i++) {
        float xv[12];
#pragma unroll
        for (int j = 0; j < 12; j++) xv[j] = xs[(tb + j) * 64 + i];
#pragma unroll
        for (int k = 0; k < 5; k++) {
            float wv = ws[o * 321 + i * 5 + k];
#pragma unroll
            for (int t = 0; t < 8; t++) acc[t] = fmaf(xv[t + k], wv, acc[t]);
        }
    }
    const int oc = ocb + o;
    float scl = rsqrtf(bvar[oc] + EPSq) * bg[oc];
    float sh = bnb[oc] - bmean[oc] * scl;
    float cbv = cb[oc];
#pragma unroll
    for (int t = 0; t < 8; t++) {
        float y = (acc[t] + cbv) * scl + sh;
        g_cv[((size_t)b * Tq + t0 + tb + t) * Hq + oc] = y / (1.f + __expf(-y));
    }
}

// ---------------- attn stage 1: q projection (coalesced, warp-per-row) -------
// grid = B, 256 threads (8 warps, 64 rows each)
__global__ __launch_bounds__(256) void attn_q(
    const float* __restrict__ qkv_w, const float* __restrict__ qkv_b)
{
    __shared__ float mg[512];
    const int b = blockIdx.x, tid = threadIdx.x;
    const int w = tid >> 5, l = tid & 31;

    if (tid < 256) {
        mg[tid]       = g_h2[((size_t)b * Tq + (Tq - 1)) * Hq + tid];
        mg[256 + tid] = g_cv[((size_t)b * Tq + (Tq - 1)) * Hq + tid];
    }
    __syncthreads();

    for (int i = 0; i < 64; i++) {
        int r = w * 64 + i;
        const float* wr = qkv_w + (size_t)r * Dq;
        float acc = 0.f;
#pragma unroll
        for (int c = 0; c < 4; c++) {
            float4 wv = *(const float4*)(wr + c * 128 + l * 4);
            const float* mv = mg + c * 128 + l * 4;
            acc += wv.x * mv[0] + wv.y * mv[1] + wv.z * mv[2] + wv.w * mv[3];
        }
        acc = warp_sum(acc);
        if (l == 0) g_q[b * Dq + r] = (acc + qkv_b[r]) * 0.125f;
    }
}

// ---------------- attn stage 2: partial softmax over T segments --------------
// grid = B*HEADS*8 = 256 CTAs; seg of 256 timesteps each. 256 threads.
__global__ __launch_bounds__(256) void attn_part()
{
    __shared__ float q[64];
    __shared__ float sc[256];
    __shared__ float red[256];
    __shared__ float vp[256];
    const int bh = blockIdx.x >> 3, seg = blockIdx.x & 7;
    const int b = bh >> 3, h = bh & 7;
    const int t0 = seg * 256;
    const int tid = threadIdx.x;
    const int w = tid >> 5, l = tid & 31;

    if (tid < 64) q[tid] = g_q[b * Dq + h * 64 + tid];
    __syncthreads();

    // scores: warp per t (32 t's per warp), coalesced k reads
    for (int i = 0; i < 32; i++) {
        int t = w * 32 + i;
        const float* kp = g_kv + ((size_t)b * Tq + t0 + t) * G4q + h * 64;
        float p = kp[l] * q[l] + kp[32 + l] * q[32 + l];
        p = warp_sum(p);
        if (l == 0) sc[t] = p;
    }
    __syncthreads();

    float m;
    red[tid] = sc[tid]; __syncthreads();
    for (int s = 128; s > 0; s >>= 1) {
        if (tid < s) red[tid] = fmaxf(red[tid], red[tid + s]);
        __syncthreads();
    }
    m = red[0];
    __syncthreads();

    float pe = __expf(sc[tid] - m);
    sc[tid] = pe;
    red[tid] = pe; __syncthreads();
    for (int s = 128; s > 0; s >>= 1) {
        if (tid < s) red[tid] += red[tid + s];
        __syncthreads();
    }
    float ssum = red[0];
    __syncthreads();

    // weighted V: threads (d = tid&63, group = tid>>6) each sum 64 t's
    const int d = tid & 63, gg = tid >> 6;
    float acc = 0.f;
    for (int t = gg * 64; t < (gg + 1) * 64; t++)
        acc = fmaf(sc[t], g_kv[((size_t)b * Tq + t0 + t) * G4q + 512 + h * 64 + d], acc);
    vp[tid] = acc; __syncthreads();

    float* part = g_part + ((size_t)bh * 8 + seg) * 66;
    if (tid == 0) { part[0] = m; part[1] = ssum; }
    if (tid < 64)
        part[2 + tid] = vp[tid] + vp[64 + tid] + vp[128 + tid] + vp[192 + tid];
}

// ---------------- attn stage 3: combine partials ----------------
// grid = B*HEADS = 32 CTAs, 64 threads
__global__ __launch_bounds__(64) void attn_comb()
{
    __shared__ float ms[8], ss[8];
    const int bh = blockIdx.x;
    const int b = bh >> 3, h = bh & 7;
    const int tid = threadIdx.x;
    const float* part = g_part + (size_t)bh * 8 * 66;

    if (tid < 8) { ms[tid] = part[tid * 66]; ss[tid] = part[tid * 66 + 1]; }
    __syncthreads();

    float M = ms[0];
#pragma unroll
    for (int j = 1; j < 8; j++) M = fmaxf(M, ms[j]);
    float denom = 0.f, num = 0.f;
#pragma unroll
    for (int j = 0; j < 8; j++) {
        float sc = __expf(ms[j] - M);
        denom += ss[j] * sc;
        num = fmaf(part[j * 66 + 2 + tid], sc, num);
    }
    g_at[b * Dq + h * 64 + tid] = num / denom;
}

// ---------------- head (warp-per-row coalesced matvecs) ----------------
// grid = B, 512 threads (16 warps)
__global__ __launch_bounds__(512) void head_kernel(
    const float* __restrict__ pw, const float* __restrict__ pb,
    const float* __restrict__ lng, const float* __restrict__ lnb,
    const float* __restrict__ f1w, const float* __restrict__ f1b,
    const float* __restrict__ f2w, const float* __restrict__ f2b,
    float* __restrict__ out)
{
    __shared__ float a[Dq], zs[Dq], zn[Dq], z2[Hq], red[512];
    const int b = blockIdx.x, tid = threadIdx.x;
    const int w = tid >> 5, l = tid & 31;

    a[tid] = g_at[b * Dq + tid];
    __syncthreads();

    // proj: 512 rows / 16 warps = 32 rows per warp
    for (int i = 0; i < 32; i++) {
        int r = w * 32 + i;
        const float* wr = pw + (size_t)r * Dq;
        float acc = 0.f;
#pragma unroll
        for (int c = 0; c < 4; c++) {
            float4 wv = *(const float4*)(wr + c * 128 + l * 4);
            const float* av = a + c * 128 + l * 4;
            acc += wv.x * av[0] + wv.y * av[1] + wv.z * av[2] + wv.w * av[3];
        }
        acc = warp_sum(acc);
        if (l == 0) {
            float mrg = (r < 256) ? g_h2[((size_t)b * Tq + Tq - 1) * Hq + r]
                                  : g_cv[((size_t)b * Tq + Tq - 1) * Hq + r - 256];
            zs[r] = acc + pb[r] + mrg;
        }
    }
    __syncthreads();

    float z = zs[tid];
    red[tid] = z; __syncthreads();
    for (int s = 256; s > 0; s >>= 1) {
        if (tid < s) red[tid] += red[tid + s];
        __syncthreads();
    }
    float mu = red[0] / 512.f;
    __syncthreads();
    float dv = z - mu;
    red[tid] = dv * dv; __syncthreads();
    for (int s = 256; s > 0; s >>= 1) {
        if (tid < s) red[tid] += red[tid + s];
        __syncthreads();
    }
    float var = red[0] / 512.f;
    __syncthreads();

    zn[tid] = dv * rsqrtf(var + EPSq) * lng[tid] + lnb[tid];
    __syncthreads();

    // fc1: 256 rows / 16 warps = 16 rows per warp
    for (int i = 0; i < 16; i++) {
        int r = w * 16 + i;
        const float* wr = f1w + (size_t)r * Dq;
        float acc = 0.f;
#pragma unroll
        for (int c = 0; c < 4; c++) {
            float4 wv = *(const float4*)(wr + c * 128 + l * 4);
            const float* av = zn + c * 128 + l * 4;
            acc += wv.x * av[0] + wv.y * av[1] + wv.z * av[2] + wv.w * av[3];
        }
        acc = warp_sum(acc);
        if (l == 0) {
            float v = acc + f1b[r];
            z2[r] = v / (1.f + expf(-v));
        }
    }
    __syncthreads();

    // fc2 (3 rows, k=256) + activations: warp 0
    if (w == 0) {
        for (int r = 0; r < 3; r++) {
            const float* wr = f2w + r * 256;
            float acc = 0.f;
#pragma unroll
            for (int c = 0; c < 2; c++) {
                float4 wv = *(const float4*)(wr + c * 128 + l * 4);
                const float* av = z2 + c * 128 + l * 4;
                acc += wv.x * av[0] + wv.y * av[1] + wv.z * av[2] + wv.w * av[3];
            }
            acc = warp_sum(acc);
            if (l == 0) {
                float lg = acc + f2b[r];
                if (r == 0)      out[b]     = tanhf(lg);
                else if (r == 1) out[4 + b] = (lg > 20.f) ? lg : log1pf(expf(lg));
                else             out[8 + b] = 1.f / (1.f + expf(-lg));
            }
        }
    }
}

// ---------------- launch ----------------
extern "C" void kernel_launch(void* const* d_in, const int* in_sizes, int n_in,
                              void* d_out, int out_size) {
    const float* x     = (const float*)d_in[0];
    const float* wih0  = (const float*)d_in[1];
    const float* whh0  = (const float*)d_in[2];
    const float* bih0  = (const float*)d_in[3];
    const float* bhh0  = (const float*)d_in[4];
    const float* wih1  = (const float*)d_in[5];
    const float* whh1  = (const float*)d_in[6];
    const float* bih1  = (const float*)d_in[7];
    const float* bhh1  = (const float*)d_in[8];
    const float* cw    = (const float*)d_in[9];
    const float* cb    = (const float*)d_in[10];
    const float* bng   = (const float*)d_in[11];
    const float* bnb   = (const float*)d_in[12];
    const float* bnm   = (const float*)d_in[13];
    const float* bnv   = (const float*)d_in[14];
    const float* qkvw  = (const float*)d_in[15];
    const float* qkvb  = (const float*)d_in[16];
    const float* pw    = (const float*)d_in[17];
    const float* pbv   = (const float*)d_in[18];
    const float* lng   = (const float*)d_in[19];
    const float* lnb   = (const float*)d_in[20];
    const float* f1w   = (const float*)d_in[21];
    const float* f1b   = (const float*)d_in[22];
    const float* f2w   = (const float*)d_in[23];
    const float* f2b   = (const float*)d_in[24];
    float* out = (float*)d_out;

    float *gx0, *gx1, *h1, *h2, *kv;
    cudaGetSymbolAddress((void**)&gx0, g_gx0);
    cudaGetSymbolAddress((void**)&gx1, g_gx1);
    cudaGetSymbolAddress((void**)&h1,  g_h1);
    cudaGetSymbolAddress((void**)&h2,  g_h2);
    cudaGetSymbolAddress((void**)&kv,  g_kv);

    const int conv_smem = (36 * 64 + 64 * 321) * 4;
    const int mega_smem = (2048 + 1024) * 4;   // 12 KB
    cudaFuncSetAttribute(conv_bn_silu, cudaFuncAttributeMaxDynamicSharedMemorySize, conv_smem);

    // 0: reset chunk flags (graph-replay determinism)
    reset_flags<<<1, 256>>>();
    // 1: conv branch (full-chip, completes before mega; kv role reads g_cv)
    conv_bn_silu<<<dim3(64, 4, 4), 256, conv_smem>>>(x, cw, cb, bng, bnb, bnm, bnv);
    // 2: fused pipeline: gx0 -> scan0 -> gx1 -> scan1 -> kv, chunk-overlapped
    mega<<<128, 256, mega_smem>>>(x, wih0, whh0, bih0, bhh0,
                                  wih1, whh1, bih1, bhh1,
                                  qkvw, qkvb,
                                  gx0, gx1, h1, h2, kv);
    // 3: attention, parallel/coalesced: q proj -> partial softmax -> combine
    attn_q<<<4, 256>>>(qkvw, qkvb);
    attn_part<<<256, 256>>>();
    attn_comb<<<32, 64>>>();
    // 4: head (warp-per-row coalesced)
    head_kernel<<<4, 512>>>(pw, pbv, lng, lnb, f1w, f1b, f2w, f2b, out);
}